// round 1
// baseline (speedup 1.0000x reference)
#include <cuda_runtime.h>
#include <cstdint>
#include <cstddef>

#define BS      64
#define NVAL    25200
#define KCAND   512
#define MAXDET  300
#define CONF_T  0.25f
#define IOU_T   0.45f
#define MAX_WH  7680.0f

// Scratch (static device globals; no allocation anywhere)
__device__ unsigned long long g_keys[(size_t)BS * NVAL];   // 12.9 MB
__device__ unsigned int       g_hist[BS][256];

// ---------------------------------------------------------------------------
// Kernel 0: zero per-image histograms (graph replays need fresh state)
// ---------------------------------------------------------------------------
__global__ void zero_hist_kernel() {
    int t = blockIdx.x * blockDim.x + threadIdx.x;
    if (t < BS * 256) ((unsigned int*)g_hist)[t] = 0u;
}

// ---------------------------------------------------------------------------
// Kernel 1: score = obj * cls, best/argmax, build 64-bit sortable keys +
//           per-image MSB histogram (radix-select pass 1 for free).
// ---------------------------------------------------------------------------
__global__ void score_kernel(const float* __restrict__ pred) {
    int b = blockIdx.y;
    int i = blockIdx.x * blockDim.x + threadIdx.x;
    __shared__ unsigned int sh[256];
    if (threadIdx.x < 256) sh[threadIdx.x] = 0u;
    __syncthreads();
    if (i < NVAL) {
        const float4* p = (const float4*)(pred + ((size_t)b * NVAL + i) * 8);
        float4 c = p[1];                 // obj, cls0, cls1, cls2
        float s0 = __fmul_rn(c.x, c.y);
        float s1 = __fmul_rn(c.x, c.z);
        float s2 = __fmul_rn(c.x, c.w);
        float best = s0;
        if (s1 > best) best = s1;
        if (s2 > best) best = s2;
        unsigned int bits = __float_as_uint(best);   // scores >= 0 -> monotonic
        g_keys[(size_t)b * NVAL + i] =
            ((unsigned long long)bits << 32) | (0xFFFFFFFFu - (unsigned int)i);
        atomicAdd(&sh[bits >> 24], 1u);
    }
    __syncthreads();
    if (threadIdx.x < 256 && sh[threadIdx.x])
        atomicAdd(&g_hist[b][threadIdx.x], sh[threadIdx.x]);
}

// ---------------------------------------------------------------------------
// Kernel 2: per-image exact top-512 (radix select on distinct 64-bit keys),
//           bitonic sort, class-aware greedy NMS, reference-exact packing.
// One block per image, 1024 threads.
// Dynamic smem layout (53248 B):
//   [0,      4096)  keys_s  : 512 x u64 candidates
//   [4096,  36864)  mask    : 512 rows x 8 u64 suppression words
//   [36864, 49152)  ox1,oy1,ox2,oy2,area,score : 6 x 512 f32
//   [49152, 53248)  cid, topi : 2 x 512 i32
// ---------------------------------------------------------------------------
extern __shared__ unsigned char smdyn[];

__global__ void __launch_bounds__(1024, 1)
nms_kernel(const float* __restrict__ pred, float* __restrict__ out) {
    const int b   = blockIdx.x;
    const int tid = threadIdx.x;

    unsigned long long* keys_s = (unsigned long long*)(smdyn);
    unsigned long long* maskA  = (unsigned long long*)(smdyn + 4096);
    float* ox1   = (float*)(smdyn + 36864);
    float* oy1   = ox1 + KCAND;
    float* ox2   = oy1 + KCAND;
    float* oy2   = ox2 + KCAND;
    float* areaA = oy2 + KCAND;
    float* scoreA= areaA + KCAND;
    int*   cidA  = (int*)(smdyn + 49152);
    int*   topiA = cidA + KCAND;

    __shared__ unsigned int hist[256];
    __shared__ unsigned long long s_prefix;
    __shared__ int s_shift, s_done, s_need, s_nv;
    __shared__ unsigned int s_cnt;
    __shared__ short vlist[KCAND], ilist[KCAND];

    const unsigned long long* keys = g_keys + (size_t)b * NVAL;

    // ---- radix select: find threshold with exactly 512 keys >= it ----
    if (tid < 256) hist[tid] = g_hist[b][tid];       // pass-1 hist precomputed
    if (tid == 0) { s_done = 0; s_need = KCAND; s_prefix = 0ull; s_shift = 64; }
    __syncthreads();

    while (true) {
        if (tid == 0) {
            int need = s_need;
            int cum = 0, bin = 255;
            for (; bin >= 0; --bin) { cum += (int)hist[bin]; if (cum >= need) break; }
            int greater  = cum - (int)hist[bin];
            int need_new = need - greater;
            s_prefix = (s_prefix << 8) | (unsigned int)bin;
            s_shift -= 8;
            s_need = need_new;
            if ((int)hist[bin] == need_new || s_shift == 0) s_done = 1;
        }
        __syncthreads();
        if (s_done) break;
        if (tid < 256) hist[tid] = 0u;
        __syncthreads();
        {
            unsigned long long pf = s_prefix;
            int sh = s_shift;
            for (int i = tid; i < NVAL; i += 1024) {
                unsigned long long kk = keys[i];
                if ((kk >> sh) == pf)
                    atomicAdd(&hist[(unsigned int)(kk >> (sh - 8)) & 255u], 1u);
            }
        }
        __syncthreads();
    }

    // ---- compact exactly 512 keys >= threshold ----
    if (tid == 0) s_cnt = 0u;
    __syncthreads();
    {
        unsigned long long pf = s_prefix;
        int sh = s_shift;
        for (int i = tid; i < NVAL; i += 1024) {
            unsigned long long kk = keys[i];
            if ((kk >> sh) >= pf) {
                unsigned int pos = atomicAdd(&s_cnt, 1u);
                keys_s[pos] = kk;
            }
        }
    }
    __syncthreads();

    // ---- bitonic sort descending (keys distinct -> deterministic order) ----
    for (int kk = 2; kk <= KCAND; kk <<= 1) {
        for (int j = kk >> 1; j > 0; j >>= 1) {
            if (tid < KCAND) {
                int ixj = tid ^ j;
                if (ixj > tid) {
                    bool dirDesc = ((tid & kk) == 0);
                    unsigned long long a = keys_s[tid], c = keys_s[ixj];
                    bool sw = dirDesc ? (a < c) : (a > c);
                    if (sw) { keys_s[tid] = c; keys_s[ixj] = a; }
                }
            }
            __syncthreads();
        }
    }

    // ---- extract candidate data (offset boxes, areas, cid, topi) ----
    if (tid < KCAND) {
        unsigned long long kk = keys_s[tid];
        int   idx = (int)(0xFFFFFFFFu - (unsigned int)kk);
        float sc  = __uint_as_float((unsigned int)(kk >> 32));
        const float4* p = (const float4*)(pred + ((size_t)b * NVAL + idx) * 8);
        float4 a = p[0];                 // cx, cy, w, h
        float4 c = p[1];                 // obj, cls0, cls1, cls2
        float s0 = __fmul_rn(c.x, c.y);
        float s1 = __fmul_rn(c.x, c.z);
        float s2 = __fmul_rn(c.x, c.w);
        int cid = 0; float bv = s0;
        if (s1 > bv) { bv = s1; cid = 1; }
        if (s2 > bv) { bv = s2; cid = 2; }
        float hw  = __fmul_rn(a.z, 0.5f), hh = __fmul_rn(a.w, 0.5f);
        float bx1 = __fsub_rn(a.x, hw),  by1 = __fsub_rn(a.y, hh);
        float bx2 = __fadd_rn(a.x, hw),  by2 = __fadd_rn(a.y, hh);
        float off = __fmul_rn((float)cid, MAX_WH);
        float X1 = __fadd_rn(bx1, off), Y1 = __fadd_rn(by1, off);
        float X2 = __fadd_rn(bx2, off), Y2 = __fadd_rn(by2, off);
        ox1[tid] = X1; oy1[tid] = Y1; ox2[tid] = X2; oy2[tid] = Y2;
        areaA[tid]  = __fmul_rn(__fsub_rn(X2, X1), __fsub_rn(Y2, Y1));
        scoreA[tid] = sc;
        cidA[tid]   = cid;
        topiA[tid]  = idx;
    }
    __syncthreads();

    // ---- pairwise IoU suppression bitmask: 512 rows x 8 u64 (j > i only) ----
    for (int t2 = tid; t2 < KCAND * 8; t2 += 1024) {
        int i = t2 >> 3, w = t2 & 7;
        float ax1 = ox1[i], ay1 = oy1[i], ax2 = ox2[i], ay2 = oy2[i], aa = areaA[i];
        unsigned long long word = 0ull;
        int jbase = w << 6;
        for (int bb = 0; bb < 64; ++bb) {
            int j = jbase + bb;
            if (j > i) {
                float ltx = fmaxf(ax1, ox1[j]), lty = fmaxf(ay1, oy1[j]);
                float rbx = fminf(ax2, ox2[j]), rby = fminf(ay2, oy2[j]);
                float iw = fmaxf(__fsub_rn(rbx, ltx), 0.0f);
                float ih = fmaxf(__fsub_rn(rby, lty), 0.0f);
                float inter = __fmul_rn(iw, ih);
                float denom = __fadd_rn(__fsub_rn(__fadd_rn(aa, areaA[j]), inter), 1e-7f);
                float iou = __fdiv_rn(inter, denom);
                if (iou > IOU_T) word |= (1ull << bb);
            }
        }
        maskA[i * 8 + w] = word;
    }
    __syncthreads();

    // ---- serial greedy scan (thread 0), sup state fully in registers ----
    if (tid == 0) {
        unsigned long long sup[8] = {0,0,0,0,0,0,0,0};
        int nv = 0, ni = 0, kc = 0;
        #pragma unroll
        for (int w = 0; w < 8; ++w) {
            for (int bb = 0; bb < 64; ++bb) {
                int i = (w << 6) + bb;
                if (!((sup[w] >> bb) & 1ull)) {
                    const unsigned long long* row = &maskA[i * 8];
                    #pragma unroll
                    for (int q = 0; q < 8; ++q) sup[q] |= row[q];
                    ++kc;
                    bool valid = (scoreA[i] > CONF_T) || (kc <= 1);
                    if (valid) vlist[nv++] = (short)i;
                    else       ilist[ni++] = (short)i;
                } else {
                    ilist[ni++] = (short)i;
                }
            }
        }
        s_nv = nv;
    }
    __syncthreads();

    // ---- pack outputs: (boxes, scores, cls, ids, valid) flattened f32 ----
    if (tid < MAXDET) {
        int nv = s_nv;
        bool isv = tid < nv;
        int k  = isv ? (int)vlist[tid] : (int)ilist[tid - nv];
        int gi = topiA[k];
        float b0 = 0.f, b1 = 0.f, b2 = 0.f, b3 = 0.f, sc = 0.f;
        if (isv) {
            const float4* p = (const float4*)(pred + ((size_t)b * NVAL + gi) * 8);
            float4 a = p[0];
            float hw = __fmul_rn(a.z, 0.5f), hh = __fmul_rn(a.w, 0.5f);
            b0 = __fsub_rn(a.x, hw); b1 = __fsub_rn(a.y, hh);
            b2 = __fadd_rn(a.x, hw); b3 = __fadd_rn(a.y, hh);
            sc = scoreA[k];
        }
        const size_t scoresOff = (size_t)BS * MAXDET * 4;
        const size_t clsOff    = scoresOff + (size_t)BS * MAXDET;
        const size_t idsOff    = clsOff    + (size_t)BS * MAXDET;
        const size_t valOff    = idsOff    + (size_t)BS * MAXDET;
        size_t r = (size_t)b * MAXDET + tid;
        out[r * 4 + 0] = b0;
        out[r * 4 + 1] = b1;
        out[r * 4 + 2] = b2;
        out[r * 4 + 3] = b3;
        out[scoresOff + r] = sc;
        out[clsOff + r] = (float)cidA[k];      // NOT zeroed for pads (ref semantics)
        out[idsOff + r] = (float)(gi / 3);     // NOT zeroed for pads (ref semantics)
        out[valOff + r] = isv ? 1.0f : 0.0f;
    }
}

// ---------------------------------------------------------------------------
extern "C" void kernel_launch(void* const* d_in, const int* in_sizes, int n_in,
                              void* d_out, int out_size) {
    (void)in_sizes; (void)n_in; (void)out_size;
    const float* pred = (const float*)d_in[0];
    float* out = (float*)d_out;

    zero_hist_kernel<<<16, 1024>>>();
    score_kernel<<<dim3((NVAL + 1023) / 1024, BS), 1024>>>(pred);
    cudaFuncSetAttribute(nms_kernel,
                         cudaFuncAttributeMaxDynamicSharedMemorySize, 53248);
    nms_kernel<<<BS, 1024, 53248>>>(pred, out);
}

// round 3
// speedup vs baseline: 1.1227x; 1.1227x over previous
#include <cuda_runtime.h>
#include <cstdint>
#include <cstddef>

#define BS      64
#define NVAL    25200
#define KCAND   512
#define MAXDET  300
#define CONF_T  0.25f
#define IOU_T   0.45f
#define MAX_WH  7680.0f

typedef unsigned long long u64;

// ---- static device scratch (no allocation anywhere) ----
__device__ u64          g_keys[(size_t)BS * NVAL];        // 12.9 MB
__device__ unsigned int g_hist[BS][256];                  // zero-init; self-resetting
__device__ float        g_ox1[BS * KCAND], g_oy1[BS * KCAND];
__device__ float        g_ox2[BS * KCAND], g_oy2[BS * KCAND];
__device__ float        g_area[BS * KCAND], g_score[BS * KCAND];
__device__ int          g_cid[BS * KCAND], g_topi[BS * KCAND];
__device__ u64          g_mask[(size_t)BS * KCAND * 8];   // 2 MB

// ---------------------------------------------------------------------------
// K1: scores -> 64-bit sortable keys + per-image MSB histogram.
//     Warp-aggregated histogram atomics (bins are heavily skewed).
// ---------------------------------------------------------------------------
__global__ void score_kernel(const float* __restrict__ pred) {
    int b = blockIdx.y;
    int i = blockIdx.x * blockDim.x + threadIdx.x;
    __shared__ unsigned int sh[256];
    if (threadIdx.x < 256) sh[threadIdx.x] = 0u;
    __syncthreads();

    bool act = (i < NVAL);
    unsigned int am = __ballot_sync(0xffffffffu, act);
    if (act) {
        const float4* p = (const float4*)(pred + ((size_t)b * NVAL + i) * 8);
        float4 c = p[1];                           // obj, cls0, cls1, cls2
        float s0 = __fmul_rn(c.x, c.y);
        float s1 = __fmul_rn(c.x, c.z);
        float s2 = __fmul_rn(c.x, c.w);
        float best = s0;
        if (s1 > best) best = s1;
        if (s2 > best) best = s2;
        unsigned int bits = __float_as_uint(best); // scores >= 0 -> monotonic
        g_keys[(size_t)b * NVAL + i] =
            ((u64)bits << 32) | (0xFFFFFFFFu - (unsigned int)i);
        unsigned int bin = bits >> 24;
        unsigned int mm = __match_any_sync(am, bin);
        if ((threadIdx.x & 31) == (__ffs(mm) - 1))
            atomicAdd(&sh[bin], (unsigned int)__popc(mm));
    }
    __syncthreads();
    if (threadIdx.x < 256 && sh[threadIdx.x])
        atomicAdd(&g_hist[b][threadIdx.x], sh[threadIdx.x]);
}

// ---------------------------------------------------------------------------
// K2: per-image exact top-512 (radix select, keys distinct), bitonic sort,
//     write candidate arrays to global. One block / image, 1024 threads.
//     Also resets g_hist[b] for the next graph replay (self-cleaning state).
// ---------------------------------------------------------------------------
__global__ void __launch_bounds__(1024, 1)
select_kernel(const float* __restrict__ pred) {
    const int b   = blockIdx.x;
    const int tid = threadIdx.x;

    __shared__ u64 keys_s[KCAND];
    __shared__ unsigned int hist[256];
    __shared__ u64 s_prefix;
    __shared__ int s_shift, s_done, s_need;
    __shared__ unsigned int s_cnt;

    const u64* keys = g_keys + (size_t)b * NVAL;

    if (tid < 256) {
        hist[tid] = g_hist[b][tid];      // pass-1 hist (from score_kernel)
        g_hist[b][tid] = 0u;             // reset for next replay
    }
    if (tid == 0) { s_done = 0; s_need = KCAND; s_prefix = 0ull; s_shift = 64; }
    __syncthreads();

    while (true) {
        if (tid == 0) {
            int need = s_need;
            int cum = 0, bin = 255;
            for (; bin >= 0; --bin) { cum += (int)hist[bin]; if (cum >= need) break; }
            int greater  = cum - (int)hist[bin];
            int need_new = need - greater;
            s_prefix = (s_prefix << 8) | (unsigned int)bin;
            s_shift -= 8;
            s_need = need_new;
            if ((int)hist[bin] == need_new || s_shift == 0) s_done = 1;
        }
        __syncthreads();
        if (s_done) break;
        if (tid < 256) hist[tid] = 0u;
        __syncthreads();
        {
            u64 pf = s_prefix;
            int sh = s_shift;
            for (int i = tid; i < NVAL; i += 1024) {
                u64 kk = keys[i];
                if ((kk >> sh) == pf)
                    atomicAdd(&hist[(unsigned int)(kk >> (sh - 8)) & 255u], 1u);
            }
        }
        __syncthreads();
    }

    if (tid == 0) s_cnt = 0u;
    __syncthreads();
    {
        u64 pf = s_prefix;
        int sh = s_shift;
        for (int i = tid; i < NVAL; i += 1024) {
            u64 kk = keys[i];
            if ((kk >> sh) >= pf) {
                unsigned int pos = atomicAdd(&s_cnt, 1u);
                keys_s[pos] = kk;
            }
        }
    }
    __syncthreads();

    // bitonic sort descending (keys distinct -> deterministic order)
    for (int kk = 2; kk <= KCAND; kk <<= 1) {
        for (int j = kk >> 1; j > 0; j >>= 1) {
            if (tid < KCAND) {
                int ixj = tid ^ j;
                if (ixj > tid) {
                    bool dirDesc = ((tid & kk) == 0);
                    u64 a = keys_s[tid], c = keys_s[ixj];
                    bool sw = dirDesc ? (a < c) : (a > c);
                    if (sw) { keys_s[tid] = c; keys_s[ixj] = a; }
                }
            }
            __syncthreads();
        }
    }

    // extract candidate data -> global
    if (tid < KCAND) {
        u64 kk = keys_s[tid];
        int   idx = (int)(0xFFFFFFFFu - (unsigned int)kk);
        float sc  = __uint_as_float((unsigned int)(kk >> 32));
        const float4* p = (const float4*)(pred + ((size_t)b * NVAL + idx) * 8);
        float4 a = p[0];                 // cx, cy, w, h
        float4 c = p[1];                 // obj, cls0..2
        float s0 = __fmul_rn(c.x, c.y);
        float s1 = __fmul_rn(c.x, c.z);
        float s2 = __fmul_rn(c.x, c.w);
        int cid = 0; float bv = s0;
        if (s1 > bv) { bv = s1; cid = 1; }
        if (s2 > bv) { bv = s2; cid = 2; }
        float hw  = __fmul_rn(a.z, 0.5f), hh = __fmul_rn(a.w, 0.5f);
        float bx1 = __fsub_rn(a.x, hw),  by1 = __fsub_rn(a.y, hh);
        float bx2 = __fadd_rn(a.x, hw),  by2 = __fadd_rn(a.y, hh);
        float off = __fmul_rn((float)cid, MAX_WH);
        float X1 = __fadd_rn(bx1, off), Y1 = __fadd_rn(by1, off);
        float X2 = __fadd_rn(bx2, off), Y2 = __fadd_rn(by2, off);
        int g = b * KCAND + tid;
        g_ox1[g] = X1; g_oy1[g] = Y1; g_ox2[g] = X2; g_oy2[g] = Y2;
        g_area[g]  = __fmul_rn(__fsub_rn(X2, X1), __fsub_rn(Y2, Y1));
        g_score[g] = sc;
        g_cid[g]   = cid;
        g_topi[g]  = idx;
    }
}

// ---------------------------------------------------------------------------
// K3: suppression mask build, chip-wide. grid = (8 row-chunks, BS images),
//     512 threads. Each thread computes one 64-bit mask word (j > i only).
// ---------------------------------------------------------------------------
__global__ void __launch_bounds__(512)
mask_kernel() {
    const int b   = blockIdx.y;
    const int tid = threadIdx.x;

    __shared__ float sx1[KCAND], sy1[KCAND], sx2[KCAND], sy2[KCAND], sar[KCAND];
    {
        int g = b * KCAND + tid;
        sx1[tid] = g_ox1[g]; sy1[tid] = g_oy1[g];
        sx2[tid] = g_ox2[g]; sy2[tid] = g_oy2[g];
        sar[tid] = g_area[g];
    }
    __syncthreads();

    int i = (blockIdx.x << 6) + (tid >> 3);   // row
    int w = tid & 7;                          // mask word within row
    float ax1 = sx1[i], ay1 = sy1[i], ax2 = sx2[i], ay2 = sy2[i], aa = sar[i];
    u64 word = 0ull;
    int jbase = w << 6;
    #pragma unroll 8
    for (int bb = 0; bb < 64; ++bb) {
        int j = jbase + bb;
        if (j > i) {
            float ltx = fmaxf(ax1, sx1[j]), lty = fmaxf(ay1, sy1[j]);
            float rbx = fminf(ax2, sx2[j]), rby = fminf(ay2, sy2[j]);
            float iw = fmaxf(__fsub_rn(rbx, ltx), 0.0f);
            float ih = fmaxf(__fsub_rn(rby, lty), 0.0f);
            float inter = __fmul_rn(iw, ih);
            float denom = __fadd_rn(__fsub_rn(__fadd_rn(aa, sar[j]), inter), 1e-7f);
            float iou = __fdiv_rn(inter, denom);
            if (iou > IOU_T) word |= (1ull << bb);
        }
    }
    g_mask[((size_t)b * KCAND + i) * 8 + w] = word;
}

// ---------------------------------------------------------------------------
// K4: greedy scan (ffs-skip, register sup state) + reference-exact packing.
//     One block / image, 1024 threads.
// ---------------------------------------------------------------------------
__global__ void __launch_bounds__(1024, 1)
final_kernel(const float* __restrict__ pred, float* __restrict__ out) {
    const int b   = blockIdx.x;
    const int tid = threadIdx.x;

    __shared__ u64 maskS[KCAND * 8];          // 32 KB
    __shared__ float scoreS[KCAND];
    __shared__ short vlist[KCAND];
    __shared__ u64 s_valid[8];
    __shared__ int s_nv;

    {
        const u64* m = g_mask + (size_t)b * KCAND * 8;
        for (int t = tid; t < KCAND * 8; t += 1024) maskS[t] = m[t];
        if (tid < KCAND) scoreS[tid] = g_score[b * KCAND + tid];
    }
    __syncthreads();

    if (tid == 0) {
        u64 sup[8] = {0,0,0,0,0,0,0,0};
        u64 vmask[8] = {0,0,0,0,0,0,0,0};
        int nv = 0, kc = 0;
        #pragma unroll
        for (int w = 0; w < 8; ++w) {
            u64 notsup = ~sup[w];
            while (notsup) {
                int bb = __ffsll((long long)notsup) - 1;
                int i = (w << 6) + bb;
                const u64* row = &maskS[i * 8];
                #pragma unroll
                for (int q = 0; q < 8; ++q) sup[q] |= row[q];
                ++kc;
                bool valid = (scoreS[i] > CONF_T) || (kc <= 1);
                if (valid) { vlist[nv++] = (short)i; vmask[w] |= (1ull << bb); }
                u64 above = (bb == 63) ? 0ull : (~0ull << (bb + 1));
                notsup = (~sup[w]) & above;
            }
        }
        s_nv = nv;
        #pragma unroll
        for (int q = 0; q < 8; ++q) s_valid[q] = vmask[q];
    }
    __syncthreads();

    if (tid < MAXDET) {
        int nv = s_nv;
        bool isv = tid < nv;
        int k;
        if (isv) {
            k = (int)vlist[tid];
        } else {
            // (tid-nv)-th invalid index, ascending (= reference tie order)
            int r = tid - nv;
            k = 0;
            #pragma unroll
            for (int w = 0; w < 8; ++w) {
                u64 inv = ~s_valid[w];
                int c = __popcll(inv);
                if (r < c) {
                    u64 x = inv;
                    for (int q = 0; q < r; ++q) x &= (x - 1);
                    k = (w << 6) + (__ffsll((long long)x) - 1);
                    r = -1;
                } else if (r >= 0) {
                    r -= c;
                }
            }
        }
        int g  = b * KCAND + k;
        int gi = g_topi[g];
        float b0 = 0.f, b1 = 0.f, b2 = 0.f, b3 = 0.f, sc = 0.f;
        if (isv) {
            const float4* p = (const float4*)(pred + ((size_t)b * NVAL + gi) * 8);
            float4 a = p[0];
            float hw = __fmul_rn(a.z, 0.5f), hh = __fmul_rn(a.w, 0.5f);
            b0 = __fsub_rn(a.x, hw); b1 = __fsub_rn(a.y, hh);
            b2 = __fadd_rn(a.x, hw); b3 = __fadd_rn(a.y, hh);
            sc = scoreS[k];
        }
        const size_t scoresOff = (size_t)BS * MAXDET * 4;
        const size_t clsOff    = scoresOff + (size_t)BS * MAXDET;
        const size_t idsOff    = clsOff    + (size_t)BS * MAXDET;
        const size_t valOff    = idsOff    + (size_t)BS * MAXDET;
        size_t r = (size_t)b * MAXDET + tid;
        out[r * 4 + 0] = b0;
        out[r * 4 + 1] = b1;
        out[r * 4 + 2] = b2;
        out[r * 4 + 3] = b3;
        out[scoresOff + r] = sc;
        out[clsOff + r] = (float)g_cid[g];     // NOT zeroed for pads (ref semantics)
        out[idsOff + r] = (float)(gi / 3);     // NOT zeroed for pads (ref semantics)
        out[valOff + r] = isv ? 1.0f : 0.0f;
    }
}

// ---------------------------------------------------------------------------
extern "C" void kernel_launch(void* const* d_in, const int* in_sizes, int n_in,
                              void* d_out, int out_size) {
    (void)in_sizes; (void)n_in; (void)out_size;
    const float* pred = (const float*)d_in[0];
    float* out = (float*)d_out;

    score_kernel<<<dim3((NVAL + 1023) / 1024, BS), 1024>>>(pred);
    select_kernel<<<BS, 1024>>>(pred);
    mask_kernel<<<dim3(8, BS), 512>>>();
    final_kernel<<<BS, 1024>>>(pred, out);
}

// round 5
// speedup vs baseline: 3.2285x; 2.8757x over previous
#include <cuda_runtime.h>
#include <cstdint>
#include <cstddef>

#define BS      64
#define NVAL    25200
#define KCAND   512
#define MAXDET  300
#define CONF_T  0.25f
#define IOU_T   0.45f
#define MAX_WH  7680.0f

typedef unsigned long long u64;

// ---- static device scratch (no allocation anywhere) ----
__device__ u64          g_keys[(size_t)BS * NVAL];        // 12.9 MB
__device__ unsigned int g_hist[BS][256];                  // zero-init; self-resetting
__device__ float        g_ox1[BS * KCAND], g_oy1[BS * KCAND];
__device__ float        g_ox2[BS * KCAND], g_oy2[BS * KCAND];
__device__ float        g_area[BS * KCAND], g_score[BS * KCAND];
__device__ int          g_cid[BS * KCAND], g_topi[BS * KCAND];
// transposed mask: word-major, g_tmask[(b*8 + w)*512 + i] = word w of row i
__device__ u64          g_tmask[(size_t)BS * 8 * KCAND];  // 2 MB

// ---------------------------------------------------------------------------
// K1: scores -> 64-bit sortable keys + per-image MSB histogram.
//     Warp-aggregated histogram atomics (bins heavily skewed).
// ---------------------------------------------------------------------------
__global__ void score_kernel(const float* __restrict__ pred) {
    int b = blockIdx.y;
    int i = blockIdx.x * blockDim.x + threadIdx.x;
    __shared__ unsigned int sh[256];
    if (threadIdx.x < 256) sh[threadIdx.x] = 0u;
    __syncthreads();

    bool act = (i < NVAL);
    unsigned int am = __ballot_sync(0xffffffffu, act);
    if (act) {
        const float4* p = (const float4*)(pred + ((size_t)b * NVAL + i) * 8);
        float4 c = p[1];                           // obj, cls0, cls1, cls2
        float s0 = __fmul_rn(c.x, c.y);
        float s1 = __fmul_rn(c.x, c.z);
        float s2 = __fmul_rn(c.x, c.w);
        float best = s0;
        if (s1 > best) best = s1;
        if (s2 > best) best = s2;
        unsigned int bits = __float_as_uint(best); // scores >= 0 -> monotonic
        g_keys[(size_t)b * NVAL + i] =
            ((u64)bits << 32) | (0xFFFFFFFFu - (unsigned int)i);
        unsigned int bin = bits >> 24;
        unsigned int mm = __match_any_sync(am, bin);
        if ((threadIdx.x & 31) == (__ffs(mm) - 1))
            atomicAdd(&sh[bin], (unsigned int)__popc(mm));
    }
    __syncthreads();
    if (threadIdx.x < 256 && sh[threadIdx.x])
        atomicAdd(&g_hist[b][threadIdx.x], sh[threadIdx.x]);
}

// ---------------------------------------------------------------------------
// K2: per-image exact top-512 (radix select, keys distinct), bitonic sort,
//     write candidate arrays to global. One block / image, 1024 threads.
//     Digit selection is PARALLEL (suffix scan), no serial 256-bin walk.
// ---------------------------------------------------------------------------
__global__ void __launch_bounds__(1024, 1)
select_kernel(const float* __restrict__ pred) {
    const int b   = blockIdx.x;
    const int tid = threadIdx.x;

    __shared__ u64 keys_s[KCAND];
    __shared__ unsigned int hist[257];
    __shared__ u64 s_prefix;
    __shared__ int s_shift, s_done, s_need;
    __shared__ unsigned int s_cnt;

    const u64* keys = g_keys + (size_t)b * NVAL;

    if (tid < 256) {
        hist[tid] = g_hist[b][tid];      // pass-1 hist (from score_kernel)
        g_hist[b][tid] = 0u;             // reset for next graph replay
    }
    if (tid == 0) { hist[256] = 0u; s_done = 0; s_need = KCAND;
                    s_prefix = 0ull; s_shift = 64; }
    __syncthreads();

    while (true) {
        // parallel suffix sum: hist[t] <- sum_{u>=t} hist[u]
        #pragma unroll
        for (int off = 1; off < 256; off <<= 1) {
            unsigned v = 0;
            if (tid < 256) {
                v = hist[tid] + ((tid + off < 256) ? hist[tid + off] : 0u);
            }
            __syncthreads();
            if (tid < 256) hist[tid] = v;
            __syncthreads();
        }
        // unique threshold bin: sfx[bin] >= need && sfx[bin+1] < need
        if (tid < 256) {
            unsigned sfx = hist[tid], sfx1 = hist[tid + 1];
            int need = s_need;
            if ((int)sfx >= need && (int)sfx1 < need) {
                int hbin     = (int)(sfx - sfx1);
                int need_new = need - (int)sfx1;
                s_prefix = (s_prefix << 8) | (unsigned int)tid;
                s_shift -= 8;
                s_need = need_new;
                if (hbin == need_new || s_shift == 0) s_done = 1;
            }
        }
        __syncthreads();
        if (s_done) break;
        if (tid < 256) hist[tid] = 0u;
        __syncthreads();
        {
            u64 pf = s_prefix;
            int sh = s_shift;
            for (int i = tid; i < NVAL; i += 1024) {
                u64 kk = keys[i];
                if ((kk >> sh) == pf)
                    atomicAdd(&hist[(unsigned int)(kk >> (sh - 8)) & 255u], 1u);
            }
        }
        __syncthreads();
    }

    if (tid == 0) s_cnt = 0u;
    __syncthreads();
    {
        u64 pf = s_prefix;
        int sh = s_shift;
        for (int i = tid; i < NVAL; i += 1024) {
            u64 kk = keys[i];
            if ((kk >> sh) >= pf) {
                unsigned int pos = atomicAdd(&s_cnt, 1u);
                keys_s[pos] = kk;
            }
        }
    }
    __syncthreads();

    // bitonic sort descending (keys distinct -> deterministic order)
    for (int kk = 2; kk <= KCAND; kk <<= 1) {
        for (int j = kk >> 1; j > 0; j >>= 1) {
            if (tid < KCAND) {
                int ixj = tid ^ j;
                if (ixj > tid) {
                    bool dirDesc = ((tid & kk) == 0);
                    u64 a = keys_s[tid], c = keys_s[ixj];
                    bool sw = dirDesc ? (a < c) : (a > c);
                    if (sw) { keys_s[tid] = c; keys_s[ixj] = a; }
                }
            }
            __syncthreads();
        }
    }

    // extract candidate data -> global
    if (tid < KCAND) {
        u64 kk = keys_s[tid];
        int   idx = (int)(0xFFFFFFFFu - (unsigned int)kk);
        float sc  = __uint_as_float((unsigned int)(kk >> 32));
        const float4* p = (const float4*)(pred + ((size_t)b * NVAL + idx) * 8);
        float4 a = p[0];                 // cx, cy, w, h
        float4 c = p[1];                 // obj, cls0..2
        float s0 = __fmul_rn(c.x, c.y);
        float s1 = __fmul_rn(c.x, c.z);
        float s2 = __fmul_rn(c.x, c.w);
        int cid = 0; float bv = s0;
        if (s1 > bv) { bv = s1; cid = 1; }
        if (s2 > bv) { bv = s2; cid = 2; }
        float hw  = __fmul_rn(a.z, 0.5f), hh = __fmul_rn(a.w, 0.5f);
        float bx1 = __fsub_rn(a.x, hw),  by1 = __fsub_rn(a.y, hh);
        float bx2 = __fadd_rn(a.x, hw),  by2 = __fadd_rn(a.y, hh);
        float off = __fmul_rn((float)cid, MAX_WH);
        float X1 = __fadd_rn(bx1, off), Y1 = __fadd_rn(by1, off);
        float X2 = __fadd_rn(bx2, off), Y2 = __fadd_rn(by2, off);
        int g = b * KCAND + tid;
        g_ox1[g] = X1; g_oy1[g] = Y1; g_ox2[g] = X2; g_oy2[g] = Y2;
        g_area[g]  = __fmul_rn(__fsub_rn(X2, X1), __fsub_rn(Y2, Y1));
        g_score[g] = sc;
        g_cid[g]   = cid;
        g_topi[g]  = idx;
    }
}

// ---------------------------------------------------------------------------
// K3: suppression mask, chip-wide. grid=(8 row-chunks, BS), 512 threads.
//     Thread (w, li): word w of row i = rowchunk*64+li.
//     Exact __fdiv_rn, but only on the ~0.4% of pairs with inter > 0.
// ---------------------------------------------------------------------------
__global__ void __launch_bounds__(512)
mask_kernel() {
    const int b   = blockIdx.y;
    const int ic  = blockIdx.x;            // row chunk
    const int tid = threadIdx.x;

    __shared__ float sx1[KCAND], sy1[KCAND], sx2[KCAND], sy2[KCAND], sar[KCAND];
    {
        int g = b * KCAND + tid;
        sx1[tid] = g_ox1[g]; sy1[tid] = g_oy1[g];
        sx2[tid] = g_ox2[g]; sy2[tid] = g_oy2[g];
        sar[tid] = g_area[g];
    }
    __syncthreads();

    const int w  = tid >> 6;               // j-word 0..7
    const int li = tid & 63;
    const int i  = (ic << 6) + li;         // row
    u64 word = 0ull;
    if (w >= ic) {                         // below-diagonal words are all zero
        float ax1 = sx1[i], ay1 = sy1[i], ax2 = sx2[i], ay2 = sy2[i], aa = sar[i];
        int jbase = w << 6;
        #pragma unroll 4
        for (int bb = 0; bb < 64; ++bb) {
            int j = jbase + bb;            // same j across warp -> smem broadcast
            float ltx = fmaxf(ax1, sx1[j]), lty = fmaxf(ay1, sy1[j]);
            float rbx = fminf(ax2, sx2[j]), rby = fminf(ay2, sy2[j]);
            float iw = fmaxf(__fsub_rn(rbx, ltx), 0.0f);
            float ih = fmaxf(__fsub_rn(rby, lty), 0.0f);
            float inter = __fmul_rn(iw, ih);
            if ((j > i) && (inter > 0.0f)) {   // inter==0 -> iou==0 exactly
                float denom = __fadd_rn(__fsub_rn(__fadd_rn(aa, sar[j]), inter), 1e-7f);
                if (__fdiv_rn(inter, denom) > IOU_T) word |= (1ull << bb);
            }
        }
    }
    g_tmask[((size_t)b * 8 + w) * KCAND + i] = word;   // coalesced (lanes vary i)
}

// ---------------------------------------------------------------------------
// K4: sparsity-aware greedy scan + parallel pack. One block / image.
//     Serial section only visits NONZERO mask rows (rare with real data).
// ---------------------------------------------------------------------------
__global__ void __launch_bounds__(1024, 1)
final_kernel(const float* __restrict__ pred, float* __restrict__ out) {
    const int b   = blockIdx.x;
    const int tid = threadIdx.x;

    __shared__ u64 tm[KCAND * 8];              // 32 KB, word-major
    __shared__ unsigned int nz32[16], conf32[16], valid32[16];
    __shared__ int s_nv;

    {
        const u64* gm = g_tmask + (size_t)b * KCAND * 8;
        #pragma unroll
        for (int t = tid; t < KCAND * 8; t += 1024) tm[t] = gm[t];
    }
    __syncthreads();

    // parallel: nonzero-row bitmap + conf bitmap (ballots)
    if (tid < KCAND) {
        u64 o = tm[tid]            | tm[KCAND     + tid] |
                tm[2*KCAND + tid]  | tm[3*KCAND   + tid] |
                tm[4*KCAND + tid]  | tm[5*KCAND   + tid] |
                tm[6*KCAND + tid]  | tm[7*KCAND   + tid];
        unsigned bnz = __ballot_sync(0xffffffffu, o != 0ull);
        float sc = g_score[b * KCAND + tid];
        unsigned bcf = __ballot_sync(0xffffffffu, sc > CONF_T);
        if ((tid & 31) == 0) { nz32[tid >> 5] = bnz; conf32[tid >> 5] = bcf; }
    }
    __syncthreads();

    // serial greedy over nonzero rows only (zero rows can't change sup)
    if (tid == 0) {
        u64 sup[8] = {0,0,0,0,0,0,0,0};
        u64 nz[8];
        #pragma unroll
        for (int q = 0; q < 8; ++q)
            nz[q] = (u64)nz32[2*q] | ((u64)nz32[2*q + 1] << 32);
        #pragma unroll
        for (int w = 0; w < 8; ++w) {
            u64 x = nz[w] & ~sup[w];
            while (x) {
                int bb = __ffsll((long long)x) - 1;
                int i = (w << 6) + bb;
                #pragma unroll
                for (int q = 0; q < 8; ++q) sup[q] |= tm[q * KCAND + i];
                u64 above = (bb == 63) ? 0ull : (~0ull << (bb + 1));
                x = nz[w] & ~sup[w] & above;
            }
        }
        int nv = 0;
        #pragma unroll
        for (int w = 0; w < 8; ++w) {
            u64 conf = (u64)conf32[2*w] | ((u64)conf32[2*w + 1] << 32);
            u64 valid = (~sup[w]) & conf;
            if (w == 0) valid |= 1ull;     // index 0: never suppressed, rank 1
            valid32[2*w]     = (unsigned int)valid;
            valid32[2*w + 1] = (unsigned int)(valid >> 32);
            nv += __popcll(valid);
        }
        s_nv = nv;
    }
    __syncthreads();

    // parallel pack: tid-th valid (ascending) or (tid-nv)-th invalid (ascending)
    if (tid < MAXDET) {
        int nv = s_nv;
        bool isv = tid < nv;
        int r = isv ? tid : tid - nv;
        int k = -1;
        #pragma unroll
        for (int wi = 0; wi < 16; ++wi) {
            unsigned wv = valid32[wi];
            if (!isv) wv = ~wv;
            int c = __popc(wv);
            if (k < 0) {
                if (r < c) k = wi * 32 + __fns(wv, 0, r + 1);
                else       r -= c;
            }
        }
        int g  = b * KCAND + k;
        int gi = g_topi[g];
        float b0 = 0.f, b1 = 0.f, b2 = 0.f, b3 = 0.f, sc = 0.f;
        if (isv) {
            const float4* p = (const float4*)(pred + ((size_t)b * NVAL + gi) * 8);
            float4 a = p[0];
            float hw = __fmul_rn(a.z, 0.5f), hh = __fmul_rn(a.w, 0.5f);
            b0 = __fsub_rn(a.x, hw); b1 = __fsub_rn(a.y, hh);
            b2 = __fadd_rn(a.x, hw); b3 = __fadd_rn(a.y, hh);
            sc = g_score[g];
        }
        const size_t scoresOff = (size_t)BS * MAXDET * 4;
        const size_t clsOff    = scoresOff + (size_t)BS * MAXDET;
        const size_t idsOff    = clsOff    + (size_t)BS * MAXDET;
        const size_t valOff    = idsOff    + (size_t)BS * MAXDET;
        size_t rr = (size_t)b * MAXDET + tid;
        out[rr * 4 + 0] = b0;
        out[rr * 4 + 1] = b1;
        out[rr * 4 + 2] = b2;
        out[rr * 4 + 3] = b3;
        out[scoresOff + rr] = sc;
        out[clsOff + rr] = (float)g_cid[g];    // NOT zeroed for pads (ref semantics)
        out[idsOff + rr] = (float)(gi / 3);    // NOT zeroed for pads (ref semantics)
        out[valOff + rr] = isv ? 1.0f : 0.0f;
    }
}

// ---------------------------------------------------------------------------
extern "C" void kernel_launch(void* const* d_in, const int* in_sizes, int n_in,
                              void* d_out, int out_size) {
    (void)in_sizes; (void)n_in; (void)out_size;
    const float* pred = (const float*)d_in[0];
    float* out = (float*)d_out;

    score_kernel<<<dim3((NVAL + 1023) / 1024, BS), 1024>>>(pred);
    select_kernel<<<BS, 1024>>>(pred);
    mask_kernel<<<dim3(8, BS), 512>>>();
    final_kernel<<<BS, 1024>>>(pred, out);
}